// round 7
// baseline (speedup 1.0000x reference)
#include <cuda_runtime.h>
#include <cstdint>

// Problem constants
#define N_NODES 50000
#define E_EDGES 1600000
#define TILE_E  128
#define ROWS    132          // padded row stride (floats) for activation buffers
#define N_TILES (E_EDGES / TILE_E)   // 12500 exactly
#define GRID_MAIN 148        // persistent: 1 CTA/SM on GB300 (148 SMs)

// smem layout (in floats)
#define BUFA_OFF    22816    // after W1(4096)+b1(64)+W2(8192)+b2(128)+W3(8192)+b3(64)+W4(2048)+b4(32)
#define BUFA_FLOATS (128 * ROWS)   // 16896
#define BUFB_OFF    (BUFA_OFF + BUFA_FLOATS)   // 39712
#define BUFB_FLOATS (64 * ROWS)    // 8448
#define DST_OFF     (BUFB_OFF + BUFB_FLOATS)   // 48160 (floats)
#define SMEM_BYTES  (DST_OFF * 4 + TILE_E * 4) // 193152

__device__ float g_cnt[N_NODES];

// ---------------- packed f32x2 helpers (Blackwell) ----------------
__device__ __forceinline__ unsigned long long pack2(float x, float y) {
    unsigned long long r;
    asm("mov.b64 %0, {%1, %2};" : "=l"(r) : "f"(x), "f"(y));
    return r;
}
__device__ __forceinline__ void fma2(unsigned long long& d, unsigned long long a, unsigned long long b) {
    asm("fma.rn.f32x2 %0, %1, %2, %3;" : "=l"(d) : "l"(a), "l"(b), "l"(d));
}
__device__ __forceinline__ void unpack2(unsigned long long v, float& x, float& y) {
    asm("mov.b64 {%0, %1}, %2;" : "=f"(x), "=f"(y) : "l"(v));
}

// ---------------- fused MLP layer: [TILE_E x INd] @ [INd x OUTd] + bias, ReLU --------
// Activations are dim-major in smem: buf[k*ROWS + e].
// Thread map: tx = tid&31 owns edges tx*4..tx*4+3; ty = tid>>5 owns OUTd/8 neurons.
template<int INd, int OUTd>
__device__ __forceinline__ void mlp_layer(const float* __restrict__ Ws,
                                          const float* __restrict__ bs,
                                          const float* __restrict__ bi,
                                          float* __restrict__ bo,
                                          int tx, int ty) {
    constexpr int NT = OUTd / 8;     // neurons per thread (8, 16, 8, 4)
    constexpr int NP = NT / 2;       // f32x2 pairs per thread (4, 8, 4, 2)
    constexpr int NQ = NP / 2;       // quads for LDS.128 weight loads (2, 4, 2, 1)
    const int j0 = ty * NT;

    unsigned long long acc[4][NP];
#pragma unroll
    for (int p = 0; p < NP; p++) {
        unsigned long long bb = *(const unsigned long long*)(bs + j0 + 2 * p);
#pragma unroll
        for (int e = 0; e < 4; e++) acc[e][p] = bb;
    }

    const float* ain = bi + (tx << 2);
#pragma unroll 2
    for (int k = 0; k < INd; k++) {
        float4 a = *(const float4*)(ain + k * ROWS);
        unsigned long long ap0 = pack2(a.x, a.x);
        unsigned long long ap1 = pack2(a.y, a.y);
        unsigned long long ap2 = pack2(a.z, a.z);
        unsigned long long ap3 = pack2(a.w, a.w);
        const float* wr = Ws + k * OUTd + j0;
        // weight loads as 16B broadcast LDS.128 (j0 is 16B-aligned: NT >= 4)
#pragma unroll
        for (int q = 0; q < NQ; q++) {
            ulonglong2 w2 = *(const ulonglong2*)(wr + 4 * q);
            fma2(acc[0][2 * q],     ap0, w2.x);
            fma2(acc[1][2 * q],     ap1, w2.x);
            fma2(acc[2][2 * q],     ap2, w2.x);
            fma2(acc[3][2 * q],     ap3, w2.x);
            fma2(acc[0][2 * q + 1], ap0, w2.y);
            fma2(acc[1][2 * q + 1], ap1, w2.y);
            fma2(acc[2][2 * q + 1], ap2, w2.y);
            fma2(acc[3][2 * q + 1], ap3, w2.y);
        }
    }

    // ReLU + store (dim-major), vectorized: one float4 STS per output row chunk.
    // Edges tx*4..tx*4+3 are consecutive -> conflict-free STS.128.
#pragma unroll
    for (int p = 0; p < NP; p++) {
        int j = j0 + 2 * p;
        float lo0, hi0, lo1, hi1, lo2, hi2, lo3, hi3;
        unpack2(acc[0][p], lo0, hi0);
        unpack2(acc[1][p], lo1, hi1);
        unpack2(acc[2][p], lo2, hi2);
        unpack2(acc[3][p], lo3, hi3);
        float4 vlo = make_float4(fmaxf(lo0, 0.0f), fmaxf(lo1, 0.0f),
                                 fmaxf(lo2, 0.0f), fmaxf(lo3, 0.0f));
        float4 vhi = make_float4(fmaxf(hi0, 0.0f), fmaxf(hi1, 0.0f),
                                 fmaxf(hi2, 0.0f), fmaxf(hi3, 0.0f));
        *(float4*)(bo + j * ROWS + (tx << 2))       = vlo;
        *(float4*)(bo + (j + 1) * ROWS + (tx << 2)) = vhi;
    }
}

// ---------------- main fused kernel ----------------
__global__ __launch_bounds__(256, 1)
void gnn_fused_kernel(const float* __restrict__ x,
                      const void* __restrict__ edge_index,   // dtype sniffed at runtime
                      const float* __restrict__ edge_attr,
                      const float* __restrict__ W1, const float* __restrict__ b1,
                      const float* __restrict__ W2, const float* __restrict__ b2,
                      const float* __restrict__ W3, const float* __restrict__ b3,
                      const float* __restrict__ W4, const float* __restrict__ b4,
                      float* __restrict__ out) {
    extern __shared__ float sm[];
    float* ws   = sm;
    float* bufA = sm + BUFA_OFF;
    float* bufB = sm + BUFB_OFF;
    int*   dsts = (int*)(sm + DST_OFF);

    const int tid = threadIdx.x;
    const int tx = tid & 31;
    const int ty = tid >> 5;

    // ---- load all weights into smem once per block (persistent blocks) ----
    {
        const float* srcs[8] = { W1, b1, W2, b2, W3, b3, W4, b4 };
        const int    lens[8] = { 4096, 64, 8192, 128, 8192, 64, 2048, 32 };
        const int    offs[8] = { 0, 4096, 4160, 12352, 12480, 20672, 20736, 22784 };
#pragma unroll
        for (int s = 0; s < 8; s++) {
            const float* src = srcs[s];
            float* dst = ws + offs[s];
            for (int i = tid; i < lens[s]; i += 256) dst[i] = src[i];
        }
    }
    const float* sW1 = ws;           const float* sb1 = ws + 4096;
    const float* sW2 = ws + 4160;    const float* sb2 = ws + 12352;
    const float* sW3 = ws + 12480;   const float* sb3 = ws + 20672;
    const float* sW4 = ws + 20736;   const float* sb4 = ws + 22784;
    __syncthreads();

    // ---- sniff edge_index dtype: int64 -> high 32 bits of first entries are 0
    // (node ids < 50000); int32 -> "high word" is another random node id,
    // nonzero with overwhelming probability across 8 samples. ----
    unsigned hi_or = 0;
    {
        const unsigned long long* chk = (const unsigned long long*)edge_index;
#pragma unroll
        for (int i = 0; i < 8; i++) hi_or |= (unsigned)(chk[i] >> 32);
    }
    const bool idx64 = (hi_or == 0);
    const long long* d64 = (const long long*)edge_index + E_EDGES;  // row 1 = dst
    const int*       d32 = (const int*)edge_index + E_EDGES;

    for (int tile = blockIdx.x; tile < N_TILES; tile += gridDim.x) {
        const int base = tile * TILE_E;

        if (tid < TILE_E) {
            int d = idx64 ? (int)d64[base + tid] : d32[base + tid];
            // defensive clamp: any surprise becomes wrong-answer, not a crash
            dsts[tid] = min(max(d, 0), N_NODES - 1);
        }
        __syncthreads();

        // ---- gather: x[dst] (k 0..31) and edge_attr (k 32..63), dim-major ----
        // Warp = one edge row across 32 dims -> coalesced 128B LDG per edge.
        for (int i = tid; i < TILE_E * 32; i += 256) {
            const int e = i >> 5;
            const int k = i & 31;
            bufA[k * ROWS + e]        = x[dsts[e] * 32 + k];
            bufA[(k + 32) * ROWS + e] = edge_attr[(long long)(base + e) * 32 + k];
        }
        __syncthreads();

        mlp_layer<64, 64>(sW1, sb1, bufA, bufB, tx, ty);  __syncthreads();
        mlp_layer<64, 128>(sW2, sb2, bufB, bufA, tx, ty); __syncthreads();
        mlp_layer<128, 64>(sW3, sb3, bufA, bufB, tx, ty); __syncthreads();
        mlp_layer<64, 32>(sW4, sb4, bufB, bufA, tx, ty);  __syncthreads();

        // ---- scatter: atomic accumulate sums into out, counts into g_cnt ----
        // Lanes of a warp cover all 32 channels of one edge's node -> coalesced
        // 128B atomic wavefront per edge.
        for (int i = tid; i < TILE_E * 32; i += 256) {
            const int e = i >> 5;
            const int c = i & 31;
            atomicAdd(&out[(long long)dsts[e] * 32 + c], bufA[c * ROWS + e]);
        }
        if (tid < TILE_E) atomicAdd(&g_cnt[dsts[tid]], 1.0f);
        __syncthreads();  // protect dsts/bufA before next tile
    }
}

// ---------------- init / finalize ----------------
__global__ void zero_kernel(float* __restrict__ out) {
    int i = blockIdx.x * 256 + threadIdx.x;
    if (i < N_NODES * 32) out[i] = 0.0f;
    if (i < N_NODES) g_cnt[i] = 0.0f;
}

__global__ void div_kernel(float* __restrict__ out) {
    int i = blockIdx.x * 256 + threadIdx.x;
    if (i < N_NODES * 32) {
        out[i] = out[i] / fmaxf(g_cnt[i >> 5], 1.0f);
    }
}

extern "C" void kernel_launch(void* const* d_in, const int* in_sizes, int n_in,
                              void* d_out, int out_size) {
    const float* x  = (const float*)d_in[0];
    const void*  ei = d_in[1];
    const float* ea = (const float*)d_in[2];
    const float* W1 = (const float*)d_in[3];
    const float* b1 = (const float*)d_in[4];
    const float* W2 = (const float*)d_in[5];
    const float* b2 = (const float*)d_in[6];
    const float* W3 = (const float*)d_in[7];
    const float* b3 = (const float*)d_in[8];
    const float* W4 = (const float*)d_in[9];
    const float* b4 = (const float*)d_in[10];
    float* out = (float*)d_out;

    cudaFuncSetAttribute(gnn_fused_kernel,
                         cudaFuncAttributeMaxDynamicSharedMemorySize, SMEM_BYTES);

    const int nelem = N_NODES * 32;
    const int g = (nelem + 255) / 256;
    zero_kernel<<<g, 256>>>(out);
    gnn_fused_kernel<<<GRID_MAIN, 256, SMEM_BYTES>>>(x, ei, ea,
                                                     W1, b1, W2, b2, W3, b3, W4, b4,
                                                     out);
    div_kernel<<<g, 256>>>(out);
}

// round 12
// speedup vs baseline: 1.1928x; 1.1928x over previous
#include <cuda_runtime.h>
#include <cstdint>

// Problem constants
#define N_NODES 50000
#define E_EDGES 1600000
#define TILE_E  128
#define ROWS    132          // padded row stride (floats) for activation buffers
#define N_TILES (E_EDGES / TILE_E)   // 12500 exactly
#define GRID_MAIN 148        // persistent: 1 CTA/SM on GB300 (148 SMs)
#define NTHREADS 512         // 16 warps -> 4 per SMSP (latency hiding)

// smem layout (in floats)
#define BUFA_OFF    22816    // after W1(4096)+b1(64)+W2(8192)+b2(128)+W3(8192)+b3(64)+W4(2048)+b4(32)
#define BUFA_FLOATS (128 * ROWS)   // 16896
#define BUFB_OFF    (BUFA_OFF + BUFA_FLOATS)   // 39712
#define BUFB_FLOATS (64 * ROWS)    // 8448
#define DST_OFF     (BUFB_OFF + BUFB_FLOATS)   // 48160 (floats)
#define SMEM_BYTES  (DST_OFF * 4 + TILE_E * 4) // 193152

__device__ float g_cnt[N_NODES];

// ---------------- packed f32x2 helpers (Blackwell) ----------------
__device__ __forceinline__ unsigned long long pack2(float x, float y) {
    unsigned long long r;
    asm("mov.b64 %0, {%1, %2};" : "=l"(r) : "f"(x), "f"(y));
    return r;
}
__device__ __forceinline__ void fma2(unsigned long long& d, unsigned long long a, unsigned long long b) {
    asm("fma.rn.f32x2 %0, %1, %2, %3;" : "=l"(d) : "l"(a), "l"(b), "l"(d));
}
__device__ __forceinline__ void unpack2(unsigned long long v, float& x, float& y) {
    asm("mov.b64 {%0, %1}, %2;" : "=f"(x), "=f"(y) : "l"(v));
}

// ---------------- fused MLP layer: [TILE_E x INd] @ [INd x OUTd] + bias, ReLU --------
// Activations are dim-major in smem: buf[k*ROWS + e].
// Thread map (512 thr): tx = tid&63 owns edges 2tx..2tx+1; ty = tid>>6 owns OUTd/8 neurons.
template<int INd, int OUTd>
__device__ __forceinline__ void mlp_layer(const float* __restrict__ Ws,
                                          const float* __restrict__ bs,
                                          const float* __restrict__ bi,
                                          float* __restrict__ bo,
                                          int tx, int ty) {
    constexpr int NT = OUTd / 8;     // neurons per thread (8, 16, 8, 4)
    constexpr int NP = NT / 2;       // f32x2 pairs per thread (4, 8, 4, 2)
    constexpr int NQ = NP / 2;       // quads for LDS.128 weight loads (2, 4, 2, 1)
    const int j0 = ty * NT;

    unsigned long long acc[2][NP];
#pragma unroll
    for (int p = 0; p < NP; p++) {
        unsigned long long bb = *(const unsigned long long*)(bs + j0 + 2 * p);
        acc[0][p] = bb;
        acc[1][p] = bb;
    }

    const float* ain = bi + (tx << 1);
#pragma unroll 4
    for (int k = 0; k < INd; k++) {
        float2 a = *(const float2*)(ain + k * ROWS);
        unsigned long long ap0 = pack2(a.x, a.x);
        unsigned long long ap1 = pack2(a.y, a.y);
        const float* wr = Ws + k * OUTd + j0;
        // weight loads as 16B broadcast LDS.128 (j0 is 16B-aligned: NT >= 4)
#pragma unroll
        for (int q = 0; q < NQ; q++) {
            ulonglong2 w2 = *(const ulonglong2*)(wr + 4 * q);
            fma2(acc[0][2 * q],     ap0, w2.x);
            fma2(acc[1][2 * q],     ap1, w2.x);
            fma2(acc[0][2 * q + 1], ap0, w2.y);
            fma2(acc[1][2 * q + 1], ap1, w2.y);
        }
    }

    // ReLU + store (dim-major): float2 {edge 2tx, 2tx+1} per neuron row.
    // Lanes consecutive -> conflict-free STS.64.
#pragma unroll
    for (int p = 0; p < NP; p++) {
        int j = j0 + 2 * p;
        float lo0, hi0, lo1, hi1;
        unpack2(acc[0][p], lo0, hi0);   // edge 2tx:   neurons j, j+1
        unpack2(acc[1][p], lo1, hi1);   // edge 2tx+1: neurons j, j+1
        *(float2*)(bo + j * ROWS + (tx << 1)) =
            make_float2(fmaxf(lo0, 0.0f), fmaxf(lo1, 0.0f));
        *(float2*)(bo + (j + 1) * ROWS + (tx << 1)) =
            make_float2(fmaxf(hi0, 0.0f), fmaxf(hi1, 0.0f));
    }
}

// ---------------- main fused kernel ----------------
__global__ __launch_bounds__(NTHREADS, 1)
void gnn_fused_kernel(const float* __restrict__ x,
                      const void* __restrict__ edge_index,   // dtype sniffed at runtime
                      const float* __restrict__ edge_attr,
                      const float* __restrict__ W1, const float* __restrict__ b1,
                      const float* __restrict__ W2, const float* __restrict__ b2,
                      const float* __restrict__ W3, const float* __restrict__ b3,
                      const float* __restrict__ W4, const float* __restrict__ b4,
                      float* __restrict__ out) {
    extern __shared__ float sm[];
    float* ws   = sm;
    float* bufA = sm + BUFA_OFF;
    float* bufB = sm + BUFB_OFF;
    int*   dsts = (int*)(sm + DST_OFF);

    const int tid = threadIdx.x;
    const int tx = tid & 63;
    const int ty = tid >> 6;

    // ---- load all weights into smem once per block (persistent blocks) ----
    {
        const float* srcs[8] = { W1, b1, W2, b2, W3, b3, W4, b4 };
        const int    lens[8] = { 4096, 64, 8192, 128, 8192, 64, 2048, 32 };
        const int    offs[8] = { 0, 4096, 4160, 12352, 12480, 20672, 20736, 22784 };
#pragma unroll
        for (int s = 0; s < 8; s++) {
            const float* src = srcs[s];
            float* dst = ws + offs[s];
            for (int i = tid; i < lens[s]; i += NTHREADS) dst[i] = src[i];
        }
    }
    const float* sW1 = ws;           const float* sb1 = ws + 4096;
    const float* sW2 = ws + 4160;    const float* sb2 = ws + 12352;
    const float* sW3 = ws + 12480;   const float* sb3 = ws + 20672;
    const float* sW4 = ws + 20736;   const float* sb4 = ws + 22784;
    __syncthreads();

    // ---- sniff edge_index dtype: int64 -> high 32 bits of first entries are 0
    // (node ids < 50000); int32 -> "high word" is another random node id. ----
    unsigned hi_or = 0;
    {
        const unsigned long long* chk = (const unsigned long long*)edge_index;
#pragma unroll
        for (int i = 0; i < 8; i++) hi_or |= (unsigned)(chk[i] >> 32);
    }
    const bool idx64 = (hi_or == 0);
    const long long* d64 = (const long long*)edge_index + E_EDGES;  // row 1 = dst
    const int*       d32 = (const int*)edge_index + E_EDGES;

    for (int tile = blockIdx.x; tile < N_TILES; tile += gridDim.x) {
        const int base = tile * TILE_E;

        if (tid < TILE_E) {
            int d = idx64 ? (int)d64[base + tid] : d32[base + tid];
            // defensive clamp: any surprise becomes wrong-answer, not a crash
            dsts[tid] = min(max(d, 0), N_NODES - 1);
        }
        __syncthreads();

        // ---- gather: x[dst] (k 0..31) and edge_attr (k 32..63), dim-major ----
        // Warp = one edge row across 32 dims -> coalesced 128B LDG per edge.
        for (int i = tid; i < TILE_E * 32; i += NTHREADS) {
            const int e = i >> 5;
            const int k = i & 31;
            bufA[k * ROWS + e]        = x[dsts[e] * 32 + k];
            bufA[(k + 32) * ROWS + e] = edge_attr[(long long)(base + e) * 32 + k];
        }
        __syncthreads();

        mlp_layer<64, 64>(sW1, sb1, bufA, bufB, tx, ty);  __syncthreads();
        mlp_layer<64, 128>(sW2, sb2, bufB, bufA, tx, ty); __syncthreads();
        mlp_layer<128, 64>(sW3, sb3, bufA, bufB, tx, ty); __syncthreads();
        mlp_layer<64, 32>(sW4, sb4, bufB, bufA, tx, ty);  __syncthreads();

        // ---- scatter: atomic accumulate sums into out, counts into g_cnt ----
        // Lanes of a warp cover all 32 channels of one edge's node -> coalesced
        // 128B atomic wavefront per edge.
        for (int i = tid; i < TILE_E * 32; i += NTHREADS) {
            const int e = i >> 5;
            const int c = i & 31;
            atomicAdd(&out[(long long)dsts[e] * 32 + c], bufA[c * ROWS + e]);
        }
        if (tid < TILE_E) atomicAdd(&g_cnt[dsts[tid]], 1.0f);
        __syncthreads();  // protect dsts/bufA before next tile
    }
}

// ---------------- init / finalize ----------------
__global__ void zero_kernel(float* __restrict__ out) {
    int i = blockIdx.x * 256 + threadIdx.x;
    if (i < N_NODES * 32) out[i] = 0.0f;
    if (i < N_NODES) g_cnt[i] = 0.0f;
}

__global__ void div_kernel(float* __restrict__ out) {
    int i = blockIdx.x * 256 + threadIdx.x;
    if (i < N_NODES * 32) {
        out[i] = out[i] / fmaxf(g_cnt[i >> 5], 1.0f);
    }
}

extern "C" void kernel_launch(void* const* d_in, const int* in_sizes, int n_in,
                              void* d_out, int out_size) {
    const float* x  = (const float*)d_in[0];
    const void*  ei = d_in[1];
    const float* ea = (const float*)d_in[2];
    const float* W1 = (const float*)d_in[3];
    const float* b1 = (const float*)d_in[4];
    const float* W2 = (const float*)d_in[5];
    const float* b2 = (const float*)d_in[6];
    const float* W3 = (const float*)d_in[7];
    const float* b3 = (const float*)d_in[8];
    const float* W4 = (const float*)d_in[9];
    const float* b4 = (const float*)d_in[10];
    float* out = (float*)d_out;

    cudaFuncSetAttribute(gnn_fused_kernel,
                         cudaFuncAttributeMaxDynamicSharedMemorySize, SMEM_BYTES);

    const int nelem = N_NODES * 32;
    const int g = (nelem + 255) / 256;
    zero_kernel<<<g, 256>>>(out);
    gnn_fused_kernel<<<GRID_MAIN, NTHREADS, SMEM_BYTES>>>(x, ei, ea,
                                                          W1, b1, W2, b2, W3, b3, W4, b4,
                                                          out);
    div_kernel<<<g, 256>>>(out);
}